// round 1
// baseline (speedup 1.0000x reference)
#include <cuda_runtime.h>
#include <cstdint>

#define L_SEQ 1024
#define C_S   1024
#define DD    32      // inner dim
#define CZ    128     // pairwise dim
#define I_PER_CTA 8

// Scratch (allocation-free rule: __device__ globals)
__device__ float g_q[L_SEQ * DD];
__device__ float g_k[L_SEQ * DD];
__device__ float g_Ak[L_SEQ * CZ];

__device__ __forceinline__ unsigned f2tf(float f) {
    unsigned r;
    asm("cvt.rna.tf32.f32 %0, %1;" : "=r"(r) : "f"(f));
    return r;
}

// ---------------------------------------------------------------------------
// Phase 1: LayerNorm + projection -> q,k [L,32]; Ak[i,z] = sum_d k[i,d]*W2[z,d]
// One CTA per sequence row.
// ---------------------------------------------------------------------------
__global__ __launch_bounds__(256) void phase1_kernel(
    const float* __restrict__ x,
    const float* __restrict__ lnw, const float* __restrict__ lnb,
    const float* __restrict__ pw,  const float* __restrict__ pb,
    const float* __restrict__ ow)
{
    __shared__ float s_s[C_S];
    __shared__ float red[16];
    __shared__ float qk[2 * DD];

    const int row = blockIdx.x;
    const int tid = threadIdx.x;
    const int lane = tid & 31;
    const int wid  = tid >> 5;

    // each thread owns 4 contiguous elements
    const float4 xv = ((const float4*)(x + (size_t)row * C_S))[tid];
    float sum = xv.x + xv.y + xv.z + xv.w;
    float sq  = xv.x * xv.x + xv.y * xv.y + xv.z * xv.z + xv.w * xv.w;
#pragma unroll
    for (int o = 16; o; o >>= 1) {
        sum += __shfl_xor_sync(~0u, sum, o);
        sq  += __shfl_xor_sync(~0u, sq,  o);
    }
    if (lane == 0) { red[wid] = sum; red[8 + wid] = sq; }
    __syncthreads();
    sum = 0.f; sq = 0.f;
#pragma unroll
    for (int w = 0; w < 8; w++) { sum += red[w]; sq += red[8 + w]; }
    const float mu   = sum * (1.0f / C_S);
    const float var  = sq * (1.0f / C_S) - mu * mu;
    const float rstd = rsqrtf(var + 1e-5f);

    const float4 wv = ((const float4*)lnw)[tid];
    const float4 bv = ((const float4*)lnb)[tid];
    float4 sv;
    sv.x = (xv.x - mu) * rstd * wv.x + bv.x;
    sv.y = (xv.y - mu) * rstd * wv.y + bv.y;
    sv.z = (xv.z - mu) * rstd * wv.z + bv.z;
    sv.w = (xv.w - mu) * rstd * wv.w + bv.w;
    ((float4*)s_s)[tid] = sv;
    __syncthreads();

    // projection: 64 outputs, warp w computes d = w*8 .. w*8+7
#pragma unroll
    for (int r = 0; r < 8; r++) {
        const int d = wid * 8 + r;
        const float* wr = pw + (size_t)d * C_S;
        float acc = 0.f;
        for (int c = lane; c < C_S; c += 32)
            acc = fmaf(s_s[c], wr[c], acc);
#pragma unroll
        for (int o = 16; o; o >>= 1) acc += __shfl_xor_sync(~0u, acc, o);
        if (lane == 0) qk[d] = acc + pb[d];
    }
    __syncthreads();

    if (tid < DD)            g_q[row * DD + tid]        = qk[tid];
    else if (tid < 2 * DD)   g_k[row * DD + (tid - DD)] = qk[tid];

    if (tid < CZ) {
        float acc = 0.f;
#pragma unroll
        for (int d = 0; d < DD; d++)
            acc = fmaf(qk[DD + d], ow[tid * (2 * DD) + DD + d], acc);
        g_Ak[row * CZ + tid] = acc;   // o_b folded later as bias = ob - Ak
    }
}

// ---------------------------------------------------------------------------
// Phase 2: out[i,j,z] = sum_d q[j,d]*Ghat_i[d,z] + (o_b[z] - Ak[i,z])
//   Ghat_i[d,z] = k[i,d]*W1[z,d] + W2[z,d]   (tf32-rounded, fragment layout)
// Grid: (8 j-tiles of 128, 128 i-groups of I_PER_CTA). 256 threads / CTA.
// Warp w owns j-rows [jbase + 16w, +16); per i: 16 n-tiles x 4 k-steps of
// mma.m16n8k8.tf32, accumulators seeded with the per-i bias.
// ---------------------------------------------------------------------------
__global__ __launch_bounds__(256) void phase2_kernel(
    const float* __restrict__ ow, const float* __restrict__ ob,
    float* __restrict__ out)
{
    // fragment buffer: [kstep(4)][ntile(16)][lane(32)] -> uint2 (b0,b1)
    __shared__ uint2 frag[4 * 16 * 32];
    __shared__ __align__(8) float bias_s[CZ];

    const int tid  = threadIdx.x;
    const int lane = tid & 31;
    const int wid  = tid >> 5;
    const int jbase = blockIdx.x * 128;
    const int ibase = blockIdx.y * I_PER_CTA;

    // ---- Per-thread W preload: 8 fragment pairs owned by this thread ----
    // pair index p = tid + 256*r; decode (kstep, ntile, lane') from p.
    float w1a[8], w1b[8], w2a[8], w2b[8];
#pragma unroll
    for (int r = 0; r < 8; r++) {
        const int p  = tid + 256 * r;
        const int kk = p >> 9;
        const int n  = (p >> 5) & 15;
        const int ln = p & 31;
        const int d0 = (ln & 3) + 8 * kk;
        const int z  = 8 * n + (ln >> 2);
        w1a[r] = ow[z * (2 * DD) + d0];
        w1b[r] = ow[z * (2 * DD) + d0 + 4];
        w2a[r] = ow[z * (2 * DD) + DD + d0];
        w2b[r] = ow[z * (2 * DD) + DD + d0 + 4];
    }

    // ---- A fragments (q side), constant across all i handled by this CTA ----
    const int j0 = jbase + wid * 16 + (lane >> 2);
    unsigned a[4][4];
#pragma unroll
    for (int kk = 0; kk < 4; kk++) {
        const int d = (lane & 3) + 8 * kk;
        a[kk][0] = f2tf(g_q[j0 * DD + d]);
        a[kk][1] = f2tf(g_q[(j0 + 8) * DD + d]);
        a[kk][2] = f2tf(g_q[j0 * DD + d + 4]);
        a[kk][3] = f2tf(g_q[(j0 + 8) * DD + d + 4]);
    }

    const float* bs = bias_s + 2 * (lane & 3);
    const uint2* fp = frag + lane;

    for (int ii = 0; ii < I_PER_CTA; ii++) {
        const int i = ibase + ii;
        __syncthreads();  // previous iteration done reading frag/bias

        if (tid < CZ)
            bias_s[tid] = ob[tid] - g_Ak[i * CZ + tid];

        // build Ghat_i fragments (L1/L2-hot k row, broadcast within warp)
#pragma unroll
        for (int r = 0; r < 8; r++) {
            const int p  = tid + 256 * r;
            const int kk = p >> 9;
            const int d0 = ((p & 3) + 8 * kk);
            const float k0 = g_k[i * DD + d0];
            const float k1 = g_k[i * DD + d0 + 4];
            uint2 v;
            v.x = f2tf(fmaf(k0, w1a[r], w2a[r]));
            v.y = f2tf(fmaf(k1, w1b[r], w2b[r]));
            frag[p] = v;
        }
        __syncthreads();

        float* optr = out + ((size_t)(i * L_SEQ + j0)) * CZ + 2 * (lane & 3);

#pragma unroll
        for (int n = 0; n < 16; n++) {
            const float2 bz = *(const float2*)(bs + 8 * n);
            float c0 = bz.x, c1 = bz.y, c2 = bz.x, c3 = bz.y;
#pragma unroll
            for (int kk = 0; kk < 4; kk++) {
                const uint2 b = fp[(kk * 16 + n) * 32];
                asm volatile(
                    "mma.sync.aligned.m16n8k8.row.col.f32.tf32.tf32.f32 "
                    "{%0,%1,%2,%3},{%4,%5,%6,%7},{%8,%9},{%0,%1,%2,%3};"
                    : "+f"(c0), "+f"(c1), "+f"(c2), "+f"(c3)
                    : "r"(a[kk][0]), "r"(a[kk][1]), "r"(a[kk][2]), "r"(a[kk][3]),
                      "r"(b.x), "r"(b.y));
            }
            float2 o01; o01.x = c0; o01.y = c1;
            float2 o23; o23.x = c2; o23.y = c3;
            *(float2*)(optr + 8 * n)            = o01;   // row j0,   z0..z0+1
            *(float2*)(optr + 8 * n + 8 * CZ)   = o23;   // row j0+8, z0..z0+1
        }
    }
}

// ---------------------------------------------------------------------------
extern "C" void kernel_launch(void* const* d_in, const int* in_sizes, int n_in,
                              void* d_out, int out_size)
{
    const float* x   = (const float*)d_in[0];
    const float* lnw = (const float*)d_in[1];
    const float* lnb = (const float*)d_in[2];
    const float* pw  = (const float*)d_in[3];
    const float* pb  = (const float*)d_in[4];
    const float* ow  = (const float*)d_in[5];
    const float* ob  = (const float*)d_in[6];
    float* out = (float*)d_out;

    phase1_kernel<<<L_SEQ, 256>>>(x, lnw, lnb, pw, pb, ow);
    phase2_kernel<<<dim3(8, L_SEQ / I_PER_CTA), 256>>>(ow, ob, out);
}

// round 2
// speedup vs baseline: 1.0037x; 1.0037x over previous
#include <cuda_runtime.h>
#include <cstdint>

#define L_SEQ 1024
#define C_S   1024
#define DD    32      // inner dim
#define CZ    128     // pairwise dim
#define I_PER_CTA 8

// Scratch (allocation-free rule: __device__ globals)
__device__ float g_q[L_SEQ * DD];
__device__ float g_k[L_SEQ * DD];
__device__ float g_Ak[L_SEQ * CZ];

__device__ __forceinline__ unsigned f2tf(float f) {
    unsigned r;
    asm("cvt.rna.tf32.f32 %0, %1;" : "=r"(r) : "f"(f));
    return r;
}

// ---------------------------------------------------------------------------
// Phase 1: LayerNorm + projection -> q,k [L,32]; Ak[i,z] = sum_d k[i,d]*W2[z,d]
// One CTA per sequence row.
// ---------------------------------------------------------------------------
__global__ __launch_bounds__(256) void phase1_kernel(
    const float* __restrict__ x,
    const float* __restrict__ lnw, const float* __restrict__ lnb,
    const float* __restrict__ pw,  const float* __restrict__ pb,
    const float* __restrict__ ow)
{
    __shared__ float s_s[C_S];
    __shared__ float red[16];
    __shared__ float qk[2 * DD];

    const int row = blockIdx.x;
    const int tid = threadIdx.x;
    const int lane = tid & 31;
    const int wid  = tid >> 5;

    // each thread owns 4 contiguous elements
    const float4 xv = ((const float4*)(x + (size_t)row * C_S))[tid];
    float sum = xv.x + xv.y + xv.z + xv.w;
    float sq  = xv.x * xv.x + xv.y * xv.y + xv.z * xv.z + xv.w * xv.w;
#pragma unroll
    for (int o = 16; o; o >>= 1) {
        sum += __shfl_xor_sync(~0u, sum, o);
        sq  += __shfl_xor_sync(~0u, sq,  o);
    }
    if (lane == 0) { red[wid] = sum; red[8 + wid] = sq; }
    __syncthreads();
    sum = 0.f; sq = 0.f;
#pragma unroll
    for (int w = 0; w < 8; w++) { sum += red[w]; sq += red[8 + w]; }
    const float mu   = sum * (1.0f / C_S);
    const float var  = sq * (1.0f / C_S) - mu * mu;
    const float rstd = rsqrtf(var + 1e-5f);

    const float4 wv = ((const float4*)lnw)[tid];
    const float4 bv = ((const float4*)lnb)[tid];
    float4 sv;
    sv.x = (xv.x - mu) * rstd * wv.x + bv.x;
    sv.y = (xv.y - mu) * rstd * wv.y + bv.y;
    sv.z = (xv.z - mu) * rstd * wv.z + bv.z;
    sv.w = (xv.w - mu) * rstd * wv.w + bv.w;
    ((float4*)s_s)[tid] = sv;
    __syncthreads();

    // projection: 64 outputs, warp w computes d = w*8 .. w*8+7
#pragma unroll
    for (int r = 0; r < 8; r++) {
        const int d = wid * 8 + r;
        const float* wr = pw + (size_t)d * C_S;
        float acc = 0.f;
        for (int c = lane; c < C_S; c += 32)
            acc = fmaf(s_s[c], wr[c], acc);
#pragma unroll
        for (int o = 16; o; o >>= 1) acc += __shfl_xor_sync(~0u, acc, o);
        if (lane == 0) qk[d] = acc + pb[d];
    }
    __syncthreads();

    if (tid < DD)            g_q[row * DD + tid]        = qk[tid];
    else if (tid < 2 * DD)   g_k[row * DD + (tid - DD)] = qk[tid];

    if (tid < CZ) {
        float acc = 0.f;
#pragma unroll
        for (int d = 0; d < DD; d++)
            acc = fmaf(qk[DD + d], ow[tid * (2 * DD) + DD + d], acc);
        g_Ak[row * CZ + tid] = acc;   // o_b folded later as bias = ob - Ak
    }
}

// ---------------------------------------------------------------------------
// Phase 2: out[i,j,z] = sum_d q[j,d]*Ghat_i[d,z] + (o_b[z] - Ak[i,z])
//   Ghat_i[d,z] = k[i,d]*W1[z,d] + W2[z,d]   (tf32-rounded, fragment layout)
// Grid: (8 j-tiles of 128, 128 i-groups of I_PER_CTA). 256 threads / CTA.
// Warp w owns j-rows [jbase + 16w, +16); per i: 16 n-tiles x 4 k-steps of
// mma.m16n8k8.tf32, accumulators seeded with the per-i bias.
// ---------------------------------------------------------------------------
__global__ __launch_bounds__(256) void phase2_kernel(
    const float* __restrict__ ow, const float* __restrict__ ob,
    float* __restrict__ out)
{
    // fragment buffer: [kstep(4)][ntile(16)][lane(32)] -> uint2 (b0,b1)
    __shared__ uint2 frag[4 * 16 * 32];
    __shared__ __align__(8) float bias_s[CZ];

    const int tid  = threadIdx.x;
    const int lane = tid & 31;
    const int wid  = tid >> 5;
    const int jbase = blockIdx.x * 128;
    const int ibase = blockIdx.y * I_PER_CTA;

    // ---- Per-thread W preload: 8 fragment pairs owned by this thread ----
    // pair index p = tid + 256*r; decode (kstep, ntile, lane') from p.
    float w1a[8], w1b[8], w2a[8], w2b[8];
#pragma unroll
    for (int r = 0; r < 8; r++) {
        const int p  = tid + 256 * r;
        const int kk = p >> 9;
        const int n  = (p >> 5) & 15;
        const int ln = p & 31;
        const int d0 = (ln & 3) + 8 * kk;
        const int z  = 8 * n + (ln >> 2);
        w1a[r] = ow[z * (2 * DD) + d0];
        w1b[r] = ow[z * (2 * DD) + d0 + 4];
        w2a[r] = ow[z * (2 * DD) + DD + d0];
        w2b[r] = ow[z * (2 * DD) + DD + d0 + 4];
    }

    // ---- A fragments (q side), constant across all i handled by this CTA ----
    const int j0 = jbase + wid * 16 + (lane >> 2);
    unsigned a[4][4];
#pragma unroll
    for (int kk = 0; kk < 4; kk++) {
        const int d = (lane & 3) + 8 * kk;
        a[kk][0] = f2tf(g_q[j0 * DD + d]);
        a[kk][1] = f2tf(g_q[(j0 + 8) * DD + d]);
        a[kk][2] = f2tf(g_q[j0 * DD + d + 4]);
        a[kk][3] = f2tf(g_q[(j0 + 8) * DD + d + 4]);
    }

    const float* bs = bias_s + 2 * (lane & 3);
    const uint2* fp = frag + lane;

    for (int ii = 0; ii < I_PER_CTA; ii++) {
        const int i = ibase + ii;
        __syncthreads();  // previous iteration done reading frag/bias

        if (tid < CZ)
            bias_s[tid] = ob[tid] - g_Ak[i * CZ + tid];

        // build Ghat_i fragments (L1/L2-hot k row, broadcast within warp)
#pragma unroll
        for (int r = 0; r < 8; r++) {
            const int p  = tid + 256 * r;
            const int kk = p >> 9;
            const int d0 = ((p & 3) + 8 * kk);
            const float k0 = g_k[i * DD + d0];
            const float k1 = g_k[i * DD + d0 + 4];
            uint2 v;
            v.x = f2tf(fmaf(k0, w1a[r], w2a[r]));
            v.y = f2tf(fmaf(k1, w1b[r], w2b[r]));
            frag[p] = v;
        }
        __syncthreads();

        float* optr = out + ((size_t)(i * L_SEQ + j0)) * CZ + 2 * (lane & 3);

#pragma unroll
        for (int n = 0; n < 16; n++) {
            const float2 bz = *(const float2*)(bs + 8 * n);
            float c0 = bz.x, c1 = bz.y, c2 = bz.x, c3 = bz.y;
#pragma unroll
            for (int kk = 0; kk < 4; kk++) {
                const uint2 b = fp[(kk * 16 + n) * 32];
                asm volatile(
                    "mma.sync.aligned.m16n8k8.row.col.f32.tf32.tf32.f32 "
                    "{%0,%1,%2,%3},{%4,%5,%6,%7},{%8,%9},{%0,%1,%2,%3};"
                    : "+f"(c0), "+f"(c1), "+f"(c2), "+f"(c3)
                    : "r"(a[kk][0]), "r"(a[kk][1]), "r"(a[kk][2]), "r"(a[kk][3]),
                      "r"(b.x), "r"(b.y));
            }
            float2 o01; o01.x = c0; o01.y = c1;
            float2 o23; o23.x = c2; o23.y = c3;
            *(float2*)(optr + 8 * n)            = o01;   // row j0,   z0..z0+1
            *(float2*)(optr + 8 * n + 8 * CZ)   = o23;   // row j0+8, z0..z0+1
        }
    }
}

// ---------------------------------------------------------------------------
extern "C" void kernel_launch(void* const* d_in, const int* in_sizes, int n_in,
                              void* d_out, int out_size)
{
    const float* x   = (const float*)d_in[0];
    const float* lnw = (const float*)d_in[1];
    const float* lnb = (const float*)d_in[2];
    const float* pw  = (const float*)d_in[3];
    const float* pb  = (const float*)d_in[4];
    const float* ow  = (const float*)d_in[5];
    const float* ob  = (const float*)d_in[6];
    float* out = (float*)d_out;

    phase1_kernel<<<L_SEQ, 256>>>(x, lnw, lnb, pw, pb, ow);
    phase2_kernel<<<dim3(8, L_SEQ / I_PER_CTA), 256>>>(ow, ob, out);
}